// round 5
// baseline (speedup 1.0000x reference)
#include <cuda_runtime.h>
#include <cuda_pipeline.h>
#include <math.h>

// Problem constants (shapes fixed by the dataset)
#define NMAX 100000
#define EMAX 3200000
#define F_IN 512
#define HID  256
#define CLS  64

typedef unsigned long long u64;

// ---------------- packed fp32x2 helpers (sm_100+ PTX) ----------------
__device__ __forceinline__ u64 dup_f32x2(float x) {
    u64 r; unsigned u = __float_as_uint(x);
    asm("mov.b64 %0, {%1, %1};" : "=l"(r) : "r"(u));
    return r;
}
__device__ __forceinline__ void fma_f32x2(u64& acc, u64 a, u64 b) {
    asm("fma.rn.f32x2 %0, %1, %2, %3;" : "=l"(acc) : "l"(a), "l"(b), "l"(acc));
}
__device__ __forceinline__ float2 unpack_f32x2(u64 v) {
    unsigned lo, hi;
    asm("mov.b64 {%0, %1}, %2;" : "=r"(lo), "=r"(hi) : "l"(v));
    return make_float2(__uint_as_float(lo), __uint_as_float(hi));
}

// ---------------- device scratch (no allocations allowed) ----------------
__device__ int    g_edeg[NMAX];
__device__ float2 g_ddi[NMAX];                  // (D^-0.5, D^-1) interleaved
__device__ int    g_rowptr[NMAX + 1];
__device__ int    g_cursor[NMAX];
__device__ int    g_bsums[128];
__device__ int    g_col[EMAX];
__device__ float  g_mean1[(size_t)NMAX * HID];  // elu(x@Wm0+b)
__device__ float  g_var1 [(size_t)NMAX * HID];  // relu(x@Wv0+b)
__device__ float2 g_mv [(size_t)NMAX * CLS];    // (mean2*attn, var2*attn^2) interleaved

// ---------------- graph preprocessing ----------------
__global__ void zero_deg_kernel(int n) {
    int i = blockIdx.x * blockDim.x + threadIdx.x;
    if (i < n) g_edeg[i] = 0;
}

__global__ void count_kernel(const int* __restrict__ src, int E) {
    int e = blockIdx.x * blockDim.x + threadIdx.x;
    if (e < E) atomicAdd(&g_edeg[src[e]], 1);
}

__global__ void degfin_kernel(int n) {
    int i = blockIdx.x * blockDim.x + threadIdx.x;
    if (i < n) {
        float d = (float)(g_edeg[i] + 1);   // +1 self loop; always > 0
        g_ddi[i] = make_float2(rsqrtf(d), 1.0f / d);
    }
}

// Block-level inclusive scan (1024/block), emit exclusive prefix + block sums.
__global__ void scan1_kernel(int n) {
    __shared__ int sm[1024];
    int t = threadIdx.x;
    int i = blockIdx.x * 1024 + t;
    int v = (i < n) ? g_edeg[i] : 0;
    sm[t] = v;
    __syncthreads();
    #pragma unroll
    for (int off = 1; off < 1024; off <<= 1) {
        int add = (t >= off) ? sm[t - off] : 0;
        __syncthreads();
        sm[t] += add;
        __syncthreads();
    }
    if (i < n) g_rowptr[i] = sm[t] - v;     // exclusive within block
    if (t == 1023) g_bsums[blockIdx.x] = sm[t];
}

__global__ void scan2_kernel(int nb) {
    __shared__ int s[128];
    int t = threadIdx.x;
    if (t < nb) s[t] = g_bsums[t];
    __syncthreads();
    if (t == 0) {
        int run = 0;
        for (int b = 0; b < nb; b++) { int v = s[b]; s[b] = run; run += v; }
    }
    __syncthreads();
    if (t < nb) g_bsums[t] = s[t];
}

__global__ void scan3_kernel(int n, int E) {
    int i = blockIdx.x * blockDim.x + threadIdx.x;
    if (i < n) {
        int r = g_rowptr[i] + g_bsums[i >> 10];
        g_rowptr[i] = r;
        g_cursor[i] = r;
    }
    if (i == 0) g_rowptr[n] = E;
}

__global__ void scatter_kernel(const int* __restrict__ src,
                               const int* __restrict__ dst, int E) {
    int e = blockIdx.x * blockDim.x + threadIdx.x;
    if (e < E) {
        int s = src[e];
        int p = atomicAdd(&g_cursor[s], 1);
        g_col[p] = dst[e];
    }
}

// ---------------- GEMM0: [M,512] @ [512,256] x2, fused activations ----------------
// grid.y: 0,1 -> mean (elu, cols 0..127 / 128..255); 2,3 -> var (relu).
// cp.async double-buffered slabs (no register staging -> 2 CTAs/SM);
// packed fp32x2 FMA inner loop (2 flops/lane/instr).
__global__ void __launch_bounds__(256, 2)
gemm0_kernel(const float* __restrict__ x,
             const float* __restrict__ Wm0, const float* __restrict__ bm0,
             const float* __restrict__ Wv0, const float* __restrict__ bv0,
             int M) {
    __shared__ float As[2][128][16];   // row-major slab: A[row][k]
    __shared__ float Bs[2][16][128];
    const int K = F_IN, LDB = HID;
    int by = blockIdx.y;
    bool isMean = (by < 2);
    const float* B    = isMean ? Wm0 : Wv0;
    const float* bias = isMean ? bm0 : bv0;
    float* Cout       = isMean ? g_mean1 : g_var1;
    int coloff = (by & 1) * 128;
    int rm0 = blockIdx.x * 128;
    int tid = threadIdx.x;
    int tx = tid & 15, ty = tid >> 4;

    u64 acc2[8][4];   // 8 rows x 4 packed col-pairs (= 8 cols)
    #pragma unroll
    for (int i = 0; i < 8; i++)
        #pragma unroll
        for (int j = 0; j < 4; j++) acc2[i][j] = 0ULL;

    // per-thread copy coordinates (2 x 16B each for A and B per slab)
    int aId0 = tid * 2;
    int ar_[2], ac_[2], br_[2], bc_[2];
    bool aOk[2];
    #pragma unroll
    for (int t = 0; t < 2; t++) {
        int id = aId0 + t;
        ar_[t] = id >> 2;  ac_[t] = (id & 3) * 4;
        br_[t] = id >> 5;  bc_[t] = (id & 31) * 4;
        aOk[t] = (rm0 + ar_[t]) < M;
    }

    // issue one slab's async copies into buffer nb at k-offset k0
    auto issue_slab = [&](int nb, int k0) {
        #pragma unroll
        for (int t = 0; t < 2; t++) {
            const float* asrc = aOk[t]
                ? (x + (size_t)(rm0 + ar_[t]) * K + k0 + ac_[t]) : x;
            __pipeline_memcpy_async(&As[nb][ar_[t]][ac_[t]], asrc, 16,
                                    aOk[t] ? 0 : 16);   // zfill whole chunk if OOB
            __pipeline_memcpy_async(&Bs[nb][br_[t]][bc_[t]],
                                    B + (size_t)(k0 + br_[t]) * LDB + coloff + bc_[t],
                                    16, 0);
        }
        __pipeline_commit();
    };

    issue_slab(0, 0);
    int buf = 0;
    for (int k0 = 0; k0 < K; k0 += 16) {
        __pipeline_wait_prior(0);
        __syncthreads();                 // slab in `buf` is ready for everyone
        int kn = k0 + 16;
        bool more = (kn < K);
        if (more) issue_slab(buf ^ 1, kn);   // overlap next slab with compute
        // compute on current buffer: packed fp32x2
        #pragma unroll
        for (int k = 0; k < 16; k++) {
            u64 ra2[8], rb2[4];
            #pragma unroll
            for (int j = 0; j < 4; j++)
                rb2[j] = *(const u64*)&Bs[buf][k][tx * 8 + 2 * j];
            #pragma unroll
            for (int i = 0; i < 8; i++)
                ra2[i] = dup_f32x2(As[buf][ty * 8 + i][k]);
            #pragma unroll
            for (int i = 0; i < 8; i++)
                #pragma unroll
                for (int j = 0; j < 4; j++)
                    fma_f32x2(acc2[i][j], ra2[i], rb2[j]);
        }
        if (more) buf ^= 1;
    }

    #pragma unroll
    for (int i = 0; i < 8; i++) {
        int gr = rm0 + ty * 8 + i;
        if (gr >= M) break;
        #pragma unroll
        for (int j = 0; j < 4; j++) {
            float2 c = unpack_f32x2(acc2[i][j]);
            int gc = coloff + tx * 8 + 2 * j;
            float v0 = c.x + bias[gc];
            float v1 = c.y + bias[gc + 1];
            if (isMean) {
                v0 = (v0 > 0.f) ? v0 : expm1f(v0);
                v1 = (v1 > 0.f) ? v1 : expm1f(v1);
            } else {
                v0 = fmaxf(v0, 0.f);
                v1 = fmaxf(v1, 0.f);
            }
            Cout[(size_t)gr * HID + gc]     = v0;
            Cout[(size_t)gr * HID + gc + 1] = v1;
        }
    }
}

// ---------------- GEMM1 fused: var pass -> attn -> mean pass ----------------
// Per block: 128 rows x 64 cols; packed fp32x2 inner loops; attn stays in regs.
__global__ void gemm1_kernel(const float* __restrict__ Wm1, const float* __restrict__ bm1,
                             const float* __restrict__ Wv1, const float* __restrict__ bv1,
                             int M) {
    __shared__ float As[16][128];
    __shared__ float Bs[16][64];
    const int K = HID, LDB = CLS;
    int rm0 = blockIdx.x * 128;
    int tid = threadIdx.x;
    int tx = tid & 15, ty = tid >> 4;
    int aId0 = tid * 2;

    // ---- pass 1: var ----
    u64 acc2[8][2];
    #pragma unroll
    for (int i = 0; i < 8; i++) { acc2[i][0] = 0ULL; acc2[i][1] = 0ULL; }

    for (int k0 = 0; k0 < K; k0 += 16) {
        #pragma unroll
        for (int t = 0; t < 2; t++) {
            int id = aId0 + t;
            int ar = id >> 2, ac4 = (id & 3) * 4;
            float4 v = make_float4(0.f, 0.f, 0.f, 0.f);
            int gr = rm0 + ar;
            if (gr < M) v = *(const float4*)(g_var1 + (size_t)gr * K + k0 + ac4);
            As[ac4 + 0][ar] = v.x; As[ac4 + 1][ar] = v.y;
            As[ac4 + 2][ar] = v.z; As[ac4 + 3][ar] = v.w;
        }
        {
            int br = tid >> 4, bc = (tid & 15) * 4;
            float4 v = *(const float4*)(Wv1 + (size_t)(k0 + br) * LDB + bc);
            *(float4*)&Bs[br][bc] = v;
        }
        __syncthreads();
        #pragma unroll
        for (int k = 0; k < 16; k++) {
            u64 ra2[8], rb2[2];
            rb2[0] = *(const u64*)&Bs[k][tx * 4];
            rb2[1] = *(const u64*)&Bs[k][tx * 4 + 2];
            #pragma unroll
            for (int i = 0; i < 8; i++) ra2[i] = dup_f32x2(As[k][ty * 8 + i]);
            #pragma unroll
            for (int i = 0; i < 8; i++) {
                fma_f32x2(acc2[i][0], ra2[i], rb2[0]);
                fma_f32x2(acc2[i][1], ra2[i], rb2[1]);
            }
        }
        __syncthreads();
    }
    // epilogue 1: relu(.)+1e-6 -> attn; store v_attn (.y) now, keep attn in regs
    float attn[8][4];
    #pragma unroll
    for (int i = 0; i < 8; i++) {
        int gr = rm0 + ty * 8 + i;
        #pragma unroll
        for (int j2 = 0; j2 < 2; j2++) {
            float2 c = unpack_f32x2(acc2[i][j2]);
            #pragma unroll
            for (int h = 0; h < 2; h++) {
                int j = j2 * 2 + h;
                int gc = tx * 4 + j;
                float v = fmaxf((h ? c.y : c.x) + bv1[gc], 0.f) + 1e-6f;
                float a = expf(-v);
                attn[i][j] = a;
                if (gr < M)
                    ((float*)g_mv)[((size_t)gr * CLS + gc) * 2 + 1] = v * a * a;
            }
        }
    }

    // ---- pass 2: mean ----
    #pragma unroll
    for (int i = 0; i < 8; i++) { acc2[i][0] = 0ULL; acc2[i][1] = 0ULL; }

    for (int k0 = 0; k0 < K; k0 += 16) {
        #pragma unroll
        for (int t = 0; t < 2; t++) {
            int id = aId0 + t;
            int ar = id >> 2, ac4 = (id & 3) * 4;
            float4 v = make_float4(0.f, 0.f, 0.f, 0.f);
            int gr = rm0 + ar;
            if (gr < M) v = *(const float4*)(g_mean1 + (size_t)gr * K + k0 + ac4);
            As[ac4 + 0][ar] = v.x; As[ac4 + 1][ar] = v.y;
            As[ac4 + 2][ar] = v.z; As[ac4 + 3][ar] = v.w;
        }
        {
            int br = tid >> 4, bc = (tid & 15) * 4;
            float4 v = *(const float4*)(Wm1 + (size_t)(k0 + br) * LDB + bc);
            *(float4*)&Bs[br][bc] = v;
        }
        __syncthreads();
        #pragma unroll
        for (int k = 0; k < 16; k++) {
            u64 ra2[8], rb2[2];
            rb2[0] = *(const u64*)&Bs[k][tx * 4];
            rb2[1] = *(const u64*)&Bs[k][tx * 4 + 2];
            #pragma unroll
            for (int i = 0; i < 8; i++) ra2[i] = dup_f32x2(As[k][ty * 8 + i]);
            #pragma unroll
            for (int i = 0; i < 8; i++) {
                fma_f32x2(acc2[i][0], ra2[i], rb2[0]);
                fma_f32x2(acc2[i][1], ra2[i], rb2[1]);
            }
        }
        __syncthreads();
    }
    // epilogue 2: elu -> m_attn (.x)
    #pragma unroll
    for (int i = 0; i < 8; i++) {
        int gr = rm0 + ty * 8 + i;
        if (gr >= M) break;
        #pragma unroll
        for (int j2 = 0; j2 < 2; j2++) {
            float2 c = unpack_f32x2(acc2[i][j2]);
            #pragma unroll
            for (int h = 0; h < 2; h++) {
                int j = j2 * 2 + h;
                int gc = tx * 4 + j;
                float v = (h ? c.y : c.x) + bm1[gc];
                v = (v > 0.f) ? v : expm1f(v);
                ((float*)g_mv)[((size_t)gr * CLS + gc) * 2 + 0] = v * attn[i][j];
            }
        }
    }
}

// ------- SpMM + output fused: pull-based CSR gather, one warp per node -------
// Unroll-4 neighbor loop for MLP; (dis,di) packed as float2 (one LDG.64 each).
__global__ void spmm_final_kernel(const float* __restrict__ sample,
                                  float* __restrict__ out, int n) {
    int warp = (blockIdx.x * blockDim.x + threadIdx.x) >> 5;
    int lane = threadIdx.x & 31;
    if (warp >= n) return;
    int i = warp;
    float2 wi = g_ddi[i];
    float disi = wi.x, dii = wi.y;
    int s = g_rowptr[i], e = g_rowptr[i + 1];

    // self loop
    float4 own = ((const float4*)g_mv)[(size_t)i * 32 + lane];
    float w0s = disi * disi, w1s = dii * dii;
    float4 acc;
    acc.x = own.x * w0s; acc.y = own.y * w1s;
    acc.z = own.z * w0s; acc.w = own.w * w1s;

    int e0 = s;
    for (; e0 + 3 < e; e0 += 4) {
        int d0 = g_col[e0],     d1 = g_col[e0 + 1];
        int d2 = g_col[e0 + 2], d3 = g_col[e0 + 3];
        float2 q0 = g_ddi[d0], q1 = g_ddi[d1], q2 = g_ddi[d2], q3 = g_ddi[d3];
        float4 v0 = ((const float4*)g_mv)[(size_t)d0 * 32 + lane];
        float4 v1 = ((const float4*)g_mv)[(size_t)d1 * 32 + lane];
        float4 v2 = ((const float4*)g_mv)[(size_t)d2 * 32 + lane];
        float4 v3 = ((const float4*)g_mv)[(size_t)d3 * 32 + lane];
        float w00 = disi * q0.x, w10 = dii * q0.y;
        float w01 = disi * q1.x, w11 = dii * q1.y;
        float w02 = disi * q2.x, w12 = dii * q2.y;
        float w03 = disi * q3.x, w13 = dii * q3.y;
        acc.x = fmaf(v0.x, w00, acc.x); acc.y = fmaf(v0.y, w10, acc.y);
        acc.z = fmaf(v0.z, w00, acc.z); acc.w = fmaf(v0.w, w10, acc.w);
        acc.x = fmaf(v1.x, w01, acc.x); acc.y = fmaf(v1.y, w11, acc.y);
        acc.z = fmaf(v1.z, w01, acc.z); acc.w = fmaf(v1.w, w11, acc.w);
        acc.x = fmaf(v2.x, w02, acc.x); acc.y = fmaf(v2.y, w12, acc.y);
        acc.z = fmaf(v2.z, w02, acc.z); acc.w = fmaf(v2.w, w12, acc.w);
        acc.x = fmaf(v3.x, w03, acc.x); acc.y = fmaf(v3.y, w13, acc.y);
        acc.z = fmaf(v3.z, w03, acc.z); acc.w = fmaf(v3.w, w13, acc.w);
    }
    for (; e0 < e; e0++) {
        int d0 = g_col[e0];
        float2 q0 = g_ddi[d0];
        float w00 = disi * q0.x, w10 = dii * q0.y;
        float4 v0 = ((const float4*)g_mv)[(size_t)d0 * 32 + lane];
        acc.x = fmaf(v0.x, w00, acc.x); acc.y = fmaf(v0.y, w10, acc.y);
        acc.z = fmaf(v0.z, w00, acc.z); acc.w = fmaf(v0.w, w10, acc.w);
    }

    // fused epilogue: out = mean + sample*sqrt(var), then log_softmax over row
    float2 sp = ((const float2*)sample)[(size_t)i * 32 + lane];
    float v0 = acc.x + sp.x * sqrtf(acc.y);
    float v1 = acc.z + sp.y * sqrtf(acc.w);
    float mx = fmaxf(v0, v1);
    #pragma unroll
    for (int off = 16; off > 0; off >>= 1)
        mx = fmaxf(mx, __shfl_xor_sync(0xffffffffu, mx, off));
    float sum = expf(v0 - mx) + expf(v1 - mx);
    #pragma unroll
    for (int off = 16; off > 0; off >>= 1)
        sum += __shfl_xor_sync(0xffffffffu, sum, off);
    float l = mx + logf(sum);
    ((float2*)out)[(size_t)i * 32 + lane] = make_float2(v0 - l, v1 - l);
}

// ---------------- launch ----------------
extern "C" void kernel_launch(void* const* d_in, const int* in_sizes, int n_in,
                              void* d_out, int out_size) {
    const float* x    = (const float*)d_in[0];
    const float* Wm0  = (const float*)d_in[1];
    const float* bm0  = (const float*)d_in[2];
    const float* Wv0  = (const float*)d_in[3];
    const float* bv0  = (const float*)d_in[4];
    const float* Wm1  = (const float*)d_in[5];
    const float* bm1  = (const float*)d_in[6];
    const float* Wv1  = (const float*)d_in[7];
    const float* bv1  = (const float*)d_in[8];
    const float* samp = (const float*)d_in[9];
    const int* esrc   = (const int*)d_in[10];
    const int* edst   = (const int*)d_in[11];
    float* out        = (float*)d_out;

    int N = in_sizes[0] / F_IN;
    int E = in_sizes[10];

    int nThr = 256;
    int nBlkN = (N + nThr - 1) / nThr;
    int nBlkE = (E + nThr - 1) / nThr;
    int nScanBlk = (N + 1023) / 1024;

    // graph preprocessing -> CSR by src
    zero_deg_kernel<<<nBlkN, nThr>>>(N);
    count_kernel<<<nBlkE, nThr>>>(esrc, E);
    degfin_kernel<<<nBlkN, nThr>>>(N);
    scan1_kernel<<<nScanBlk, 1024>>>(N);
    scan2_kernel<<<1, 128>>>(nScanBlk);
    scan3_kernel<<<nBlkN, nThr>>>(N, E);
    scatter_kernel<<<nBlkE, nThr>>>(esrc, edst, E);

    // dense pipeline
    dim3 g0((N + 127) / 128, 4);
    gemm0_kernel<<<g0, 256>>>(x, Wm0, bm0, Wv0, bv0, N);
    gemm1_kernel<<<(N + 127) / 128, 256>>>(Wm1, bm1, Wv1, bv1, N);

    // sparse aggregation + fused output
    int warpsPerBlk = nThr / 32;
    spmm_final_kernel<<<(N + warpsPerBlk - 1) / warpsPerBlk, nThr>>>(samp, out, N);
}

// round 7
// speedup vs baseline: 1.1071x; 1.1071x over previous
#include <cuda_runtime.h>
#include <cuda_pipeline.h>
#include <math.h>

// Problem constants (shapes fixed by the dataset)
#define NMAX 100000
#define EMAX 3200000
#define F_IN 512
#define HID  256
#define CLS  64

typedef unsigned long long u64;

// ---------------- packed fp32x2 helpers (sm_100+ PTX) ----------------
__device__ __forceinline__ u64 dup_f32x2(float x) {
    u64 r; unsigned u = __float_as_uint(x);
    asm("mov.b64 %0, {%1, %1};" : "=l"(r) : "r"(u));
    return r;
}
__device__ __forceinline__ void fma_f32x2(u64& acc, u64 a, u64 b) {
    asm("fma.rn.f32x2 %0, %1, %2, %3;" : "=l"(acc) : "l"(a), "l"(b), "l"(acc));
}
__device__ __forceinline__ float2 unpack_f32x2(u64 v) {
    unsigned lo, hi;
    asm("mov.b64 {%0, %1}, %2;" : "=r"(lo), "=r"(hi) : "l"(v));
    return make_float2(__uint_as_float(lo), __uint_as_float(hi));
}

// ---------------- device scratch (no allocations allowed) ----------------
__device__ int    g_edeg[NMAX];
__device__ float2 g_ddi[NMAX];                  // (D^-0.5, D^-1) interleaved
__device__ int    g_rowptr[NMAX + 1];
__device__ int    g_cursor[NMAX];
__device__ int    g_bsums[128];
__device__ int    g_col[EMAX];
__device__ float  g_mean1[(size_t)NMAX * HID];  // elu(x@Wm0+b)
__device__ float  g_var1 [(size_t)NMAX * HID];  // relu(x@Wv0+b)
__device__ float2 g_mv [(size_t)NMAX * CLS];    // (mean2*attn, var2*attn^2) interleaved

// ---------------- graph preprocessing ----------------
__global__ void zero_deg_kernel(int n) {
    int i = blockIdx.x * blockDim.x + threadIdx.x;
    if (i < n) g_edeg[i] = 0;
}

__global__ void count_kernel(const int* __restrict__ src, int E) {
    int e = blockIdx.x * blockDim.x + threadIdx.x;
    if (e < E) atomicAdd(&g_edeg[src[e]], 1);
}

__global__ void degfin_kernel(int n) {
    int i = blockIdx.x * blockDim.x + threadIdx.x;
    if (i < n) {
        float d = (float)(g_edeg[i] + 1);   // +1 self loop; always > 0
        g_ddi[i] = make_float2(rsqrtf(d), 1.0f / d);
    }
}

// Block-level inclusive scan (1024/block), emit exclusive prefix + block sums.
__global__ void scan1_kernel(int n) {
    __shared__ int sm[1024];
    int t = threadIdx.x;
    int i = blockIdx.x * 1024 + t;
    int v = (i < n) ? g_edeg[i] : 0;
    sm[t] = v;
    __syncthreads();
    #pragma unroll
    for (int off = 1; off < 1024; off <<= 1) {
        int add = (t >= off) ? sm[t - off] : 0;
        __syncthreads();
        sm[t] += add;
        __syncthreads();
    }
    if (i < n) g_rowptr[i] = sm[t] - v;     // exclusive within block
    if (t == 1023) g_bsums[blockIdx.x] = sm[t];
}

__global__ void scan2_kernel(int nb) {
    __shared__ int s[128];
    int t = threadIdx.x;
    if (t < nb) s[t] = g_bsums[t];
    __syncthreads();
    if (t == 0) {
        int run = 0;
        for (int b = 0; b < nb; b++) { int v = s[b]; s[b] = run; run += v; }
    }
    __syncthreads();
    if (t < nb) g_bsums[t] = s[t];
}

__global__ void scan3_kernel(int n, int E) {
    int i = blockIdx.x * blockDim.x + threadIdx.x;
    if (i < n) {
        int r = g_rowptr[i] + g_bsums[i >> 10];
        g_rowptr[i] = r;
        g_cursor[i] = r;
    }
    if (i == 0) g_rowptr[n] = E;
}

__global__ void scatter_kernel(const int* __restrict__ src,
                               const int* __restrict__ dst, int E) {
    int e = blockIdx.x * blockDim.x + threadIdx.x;
    if (e < E) {
        int s = src[e];
        int p = atomicAdd(&g_cursor[s], 1);
        g_col[p] = dst[e];
    }
}

// ---------------- GEMM0: [M,512] @ [512,256] x2, fused activations ----------------
// grid.y: 0,1 -> mean (elu, cols 0..127 / 128..255); 2,3 -> var (relu).
// cp.async double-buffered slabs; A stored transposed As[k][row] (pad 136,
// conflict-free LDS); B thread-cols remapped to {2tx+32j} (conflict-free LDS.64);
// packed fp32x2 FMA inner loop.
__global__ void __launch_bounds__(256, 2)
gemm0_kernel(const float* __restrict__ x,
             const float* __restrict__ Wm0, const float* __restrict__ bm0,
             const float* __restrict__ Wv0, const float* __restrict__ bv0,
             int M) {
    __shared__ float As[2][16][136];   // transposed slab: A[k][row], padded
    __shared__ float Bs[2][16][128];
    const int K = F_IN, LDB = HID;
    int by = blockIdx.y;
    bool isMean = (by < 2);
    const float* B    = isMean ? Wm0 : Wv0;
    const float* bias = isMean ? bm0 : bv0;
    float* Cout       = isMean ? g_mean1 : g_var1;
    int coloff = (by & 1) * 128;
    int rm0 = blockIdx.x * 128;
    int tid = threadIdx.x;
    int tx = tid & 15, ty = tid >> 4;

    u64 acc2[8][4];   // 8 rows x 4 packed col-pairs; pair j -> cols 2tx+32j, +1
    #pragma unroll
    for (int i = 0; i < 8; i++)
        #pragma unroll
        for (int j = 0; j < 4; j++) acc2[i][j] = 0ULL;

    // B copy coordinates (2 x 16B per thread per slab)
    int aId0 = tid * 2;
    int br_[2], bc_[2];
    #pragma unroll
    for (int t = 0; t < 2; t++) {
        int id = aId0 + t;
        br_[t] = id >> 5;  bc_[t] = (id & 31) * 4;
    }

    // issue one slab's async copies into buffer nb at k-offset k0
    auto issue_slab = [&](int nb, int k0) {
        // A: 2048 floats / 256 thr = 8 x 4B cp.async each; coalesced in global,
        // transposed into As[k][row]
        #pragma unroll
        for (int j = 0; j < 8; j++) {
            int e = j * 256 + tid;
            int row = e >> 4, kk = e & 15;
            bool ok = (rm0 + row) < M;
            const float* src = ok ? (x + (size_t)(rm0 + row) * K + k0 + kk) : x;
            __pipeline_memcpy_async(&As[nb][kk][row], src, 4, ok ? 0 : 4);
        }
        #pragma unroll
        for (int t = 0; t < 2; t++) {
            __pipeline_memcpy_async(&Bs[nb][br_[t]][bc_[t]],
                                    B + (size_t)(k0 + br_[t]) * LDB + coloff + bc_[t],
                                    16, 0);
        }
        __pipeline_commit();
    };

    issue_slab(0, 0);
    int buf = 0;
    for (int k0 = 0; k0 < K; k0 += 16) {
        __pipeline_wait_prior(0);
        __syncthreads();                 // slab in `buf` is ready for everyone
        int kn = k0 + 16;
        bool more = (kn < K);
        if (more) issue_slab(buf ^ 1, kn);   // overlap next slab with compute
        // compute on current buffer: packed fp32x2
        #pragma unroll
        for (int k = 0; k < 16; k++) {
            u64 ra2[8], rb2[4];
            #pragma unroll
            for (int j = 0; j < 4; j++)
                rb2[j] = *(const u64*)&Bs[buf][k][2 * tx + 32 * j];
            #pragma unroll
            for (int i = 0; i < 8; i++)
                ra2[i] = dup_f32x2(As[buf][k][ty * 8 + i]);
            #pragma unroll
            for (int i = 0; i < 8; i++)
                #pragma unroll
                for (int j = 0; j < 4; j++)
                    fma_f32x2(acc2[i][j], ra2[i], rb2[j]);
        }
        if (more) buf ^= 1;
    }

    #pragma unroll
    for (int i = 0; i < 8; i++) {
        int gr = rm0 + ty * 8 + i;
        if (gr >= M) break;
        #pragma unroll
        for (int j = 0; j < 4; j++) {
            float2 c = unpack_f32x2(acc2[i][j]);
            int gc = coloff + 2 * tx + 32 * j;
            float v0 = c.x + bias[gc];
            float v1 = c.y + bias[gc + 1];
            if (isMean) {
                v0 = (v0 > 0.f) ? v0 : expm1f(v0);
                v1 = (v1 > 0.f) ? v1 : expm1f(v1);
            } else {
                v0 = fmaxf(v0, 0.f);
                v1 = fmaxf(v1, 0.f);
            }
            *(float2*)(Cout + (size_t)gr * HID + gc) = make_float2(v0, v1);
        }
    }
}

// ---------------- GEMM1 fused: var pass -> attn -> mean pass ----------------
// Per block: 128 rows x 64 cols; packed fp32x2 inner loops; attn stays in regs.
// Thread cols remapped to {2tx, 2tx+1, 2tx+32, 2tx+33} (conflict-free LDS.64).
__global__ void gemm1_kernel(const float* __restrict__ Wm1, const float* __restrict__ bm1,
                             const float* __restrict__ Wv1, const float* __restrict__ bv1,
                             int M) {
    __shared__ float As[16][128];
    __shared__ float Bs[16][64];
    const int K = HID, LDB = CLS;
    int rm0 = blockIdx.x * 128;
    int tid = threadIdx.x;
    int tx = tid & 15, ty = tid >> 4;
    int aId0 = tid * 2;

    // ---- pass 1: var ----
    u64 acc2[8][2];
    #pragma unroll
    for (int i = 0; i < 8; i++) { acc2[i][0] = 0ULL; acc2[i][1] = 0ULL; }

    for (int k0 = 0; k0 < K; k0 += 16) {
        #pragma unroll
        for (int t = 0; t < 2; t++) {
            int id = aId0 + t;
            int ar = id >> 2, ac4 = (id & 3) * 4;
            float4 v = make_float4(0.f, 0.f, 0.f, 0.f);
            int gr = rm0 + ar;
            if (gr < M) v = *(const float4*)(g_var1 + (size_t)gr * K + k0 + ac4);
            As[ac4 + 0][ar] = v.x; As[ac4 + 1][ar] = v.y;
            As[ac4 + 2][ar] = v.z; As[ac4 + 3][ar] = v.w;
        }
        {
            int br = tid >> 4, bc = (tid & 15) * 4;
            float4 v = *(const float4*)(Wv1 + (size_t)(k0 + br) * LDB + bc);
            *(float4*)&Bs[br][bc] = v;
        }
        __syncthreads();
        #pragma unroll
        for (int k = 0; k < 16; k++) {
            u64 ra2[8], rb2[2];
            rb2[0] = *(const u64*)&Bs[k][2 * tx];
            rb2[1] = *(const u64*)&Bs[k][2 * tx + 32];
            #pragma unroll
            for (int i = 0; i < 8; i++) ra2[i] = dup_f32x2(As[k][ty * 8 + i]);
            #pragma unroll
            for (int i = 0; i < 8; i++) {
                fma_f32x2(acc2[i][0], ra2[i], rb2[0]);
                fma_f32x2(acc2[i][1], ra2[i], rb2[1]);
            }
        }
        __syncthreads();
    }
    // epilogue 1: relu(.)+1e-6 -> attn; store v_attn (.y) now, keep attn in regs
    float attn[8][4];
    #pragma unroll
    for (int i = 0; i < 8; i++) {
        int gr = rm0 + ty * 8 + i;
        #pragma unroll
        for (int j2 = 0; j2 < 2; j2++) {
            float2 c = unpack_f32x2(acc2[i][j2]);
            #pragma unroll
            for (int h = 0; h < 2; h++) {
                int j = j2 * 2 + h;
                int gc = 2 * tx + 32 * j2 + h;
                float v = fmaxf((h ? c.y : c.x) + bv1[gc], 0.f) + 1e-6f;
                float a = expf(-v);
                attn[i][j] = a;
                if (gr < M)
                    ((float*)g_mv)[((size_t)gr * CLS + gc) * 2 + 1] = v * a * a;
            }
        }
    }

    // ---- pass 2: mean ----
    #pragma unroll
    for (int i = 0; i < 8; i++) { acc2[i][0] = 0ULL; acc2[i][1] = 0ULL; }

    for (int k0 = 0; k0 < K; k0 += 16) {
        #pragma unroll
        for (int t = 0; t < 2; t++) {
            int id = aId0 + t;
            int ar = id >> 2, ac4 = (id & 3) * 4;
            float4 v = make_float4(0.f, 0.f, 0.f, 0.f);
            int gr = rm0 + ar;
            if (gr < M) v = *(const float4*)(g_mean1 + (size_t)gr * K + k0 + ac4);
            As[ac4 + 0][ar] = v.x; As[ac4 + 1][ar] = v.y;
            As[ac4 + 2][ar] = v.z; As[ac4 + 3][ar] = v.w;
        }
        {
            int br = tid >> 4, bc = (tid & 15) * 4;
            float4 v = *(const float4*)(Wm1 + (size_t)(k0 + br) * LDB + bc);
            *(float4*)&Bs[br][bc] = v;
        }
        __syncthreads();
        #pragma unroll
        for (int k = 0; k < 16; k++) {
            u64 ra2[8], rb2[2];
            rb2[0] = *(const u64*)&Bs[k][2 * tx];
            rb2[1] = *(const u64*)&Bs[k][2 * tx + 32];
            #pragma unroll
            for (int i = 0; i < 8; i++) ra2[i] = dup_f32x2(As[k][ty * 8 + i]);
            #pragma unroll
            for (int i = 0; i < 8; i++) {
                fma_f32x2(acc2[i][0], ra2[i], rb2[0]);
                fma_f32x2(acc2[i][1], ra2[i], rb2[1]);
            }
        }
        __syncthreads();
    }
    // epilogue 2: elu -> m_attn (.x)
    #pragma unroll
    for (int i = 0; i < 8; i++) {
        int gr = rm0 + ty * 8 + i;
        if (gr >= M) break;
        #pragma unroll
        for (int j2 = 0; j2 < 2; j2++) {
            float2 c = unpack_f32x2(acc2[i][j2]);
            #pragma unroll
            for (int h = 0; h < 2; h++) {
                int j = j2 * 2 + h;
                int gc = 2 * tx + 32 * j2 + h;
                float v = (h ? c.y : c.x) + bm1[gc];
                v = (v > 0.f) ? v : expm1f(v);
                ((float*)g_mv)[((size_t)gr * CLS + gc) * 2 + 0] = v * attn[i][j];
            }
        }
    }
}

// ------- SpMM + output fused: pull-based CSR gather, one warp per node -------
// Unroll-4 neighbor loop for MLP; (dis,di) packed as float2 (one LDG.64 each).
__global__ void spmm_final_kernel(const float* __restrict__ sample,
                                  float* __restrict__ out, int n) {
    int warp = (blockIdx.x * blockDim.x + threadIdx.x) >> 5;
    int lane = threadIdx.x & 31;
    if (warp >= n) return;
    int i = warp;
    float2 wi = g_ddi[i];
    float disi = wi.x, dii = wi.y;
    int s = g_rowptr[i], e = g_rowptr[i + 1];

    // self loop
    float4 own = ((const float4*)g_mv)[(size_t)i * 32 + lane];
    float w0s = disi * disi, w1s = dii * dii;
    float4 acc;
    acc.x = own.x * w0s; acc.y = own.y * w1s;
    acc.z = own.z * w0s; acc.w = own.w * w1s;

    int e0 = s;
    for (; e0 + 3 < e; e0 += 4) {
        int d0 = g_col[e0],     d1 = g_col[e0 + 1];
        int d2 = g_col[e0 + 2], d3 = g_col[e0 + 3];
        float2 q0 = g_ddi[d0], q1 = g_ddi[d1], q2 = g_ddi[d2], q3 = g_ddi[d3];
        float4 v0 = ((const float4*)g_mv)[(size_t)d0 * 32 + lane];
        float4 v1 = ((const float4*)g_mv)[(size_t)d1 * 32 + lane];
        float4 v2 = ((const float4*)g_mv)[(size_t)d2 * 32 + lane];
        float4 v3 = ((const float4*)g_mv)[(size_t)d3 * 32 + lane];
        float w00 = disi * q0.x, w10 = dii * q0.y;
        float w01 = disi * q1.x, w11 = dii * q1.y;
        float w02 = disi * q2.x, w12 = dii * q2.y;
        float w03 = disi * q3.x, w13 = dii * q3.y;
        acc.x = fmaf(v0.x, w00, acc.x); acc.y = fmaf(v0.y, w10, acc.y);
        acc.z = fmaf(v0.z, w00, acc.z); acc.w = fmaf(v0.w, w10, acc.w);
        acc.x = fmaf(v1.x, w01, acc.x); acc.y = fmaf(v1.y, w11, acc.y);
        acc.z = fmaf(v1.z, w01, acc.z); acc.w = fmaf(v1.w, w11, acc.w);
        acc.x = fmaf(v2.x, w02, acc.x); acc.y = fmaf(v2.y, w12, acc.y);
        acc.z = fmaf(v2.z, w02, acc.z); acc.w = fmaf(v2.w, w12, acc.w);
        acc.x = fmaf(v3.x, w03, acc.x); acc.y = fmaf(v3.y, w13, acc.y);
        acc.z = fmaf(v3.z, w03, acc.z); acc.w = fmaf(v3.w, w13, acc.w);
    }
    for (; e0 < e; e0++) {
        int d0 = g_col[e0];
        float2 q0 = g_ddi[d0];
        float w00 = disi * q0.x, w10 = dii * q0.y;
        float4 v0 = ((const float4*)g_mv)[(size_t)d0 * 32 + lane];
        acc.x = fmaf(v0.x, w00, acc.x); acc.y = fmaf(v0.y, w10, acc.y);
        acc.z = fmaf(v0.z, w00, acc.z); acc.w = fmaf(v0.w, w10, acc.w);
    }

    // fused epilogue: out = mean + sample*sqrt(var), then log_softmax over row
    float2 sp = ((const float2*)sample)[(size_t)i * 32 + lane];
    float v0 = acc.x + sp.x * sqrtf(acc.y);
    float v1 = acc.z + sp.y * sqrtf(acc.w);
    float mx = fmaxf(v0, v1);
    #pragma unroll
    for (int off = 16; off > 0; off >>= 1)
        mx = fmaxf(mx, __shfl_xor_sync(0xffffffffu, mx, off));
    float sum = expf(v0 - mx) + expf(v1 - mx);
    #pragma unroll
    for (int off = 16; off > 0; off >>= 1)
        sum += __shfl_xor_sync(0xffffffffu, sum, off);
    float l = mx + logf(sum);
    ((float2*)out)[(size_t)i * 32 + lane] = make_float2(v0 - l, v1 - l);
}

// ---------------- launch ----------------
extern "C" void kernel_launch(void* const* d_in, const int* in_sizes, int n_in,
                              void* d_out, int out_size) {
    const float* x    = (const float*)d_in[0];
    const float* Wm0  = (const float*)d_in[1];
    const float* bm0  = (const float*)d_in[2];
    const float* Wv0  = (const float*)d_in[3];
    const float* bv0  = (const float*)d_in[4];
    const float* Wm1  = (const float*)d_in[5];
    const float* bm1  = (const float*)d_in[6];
    const float* Wv1  = (const float*)d_in[7];
    const float* bv1  = (const float*)d_in[8];
    const float* samp = (const float*)d_in[9];
    const int* esrc   = (const int*)d_in[10];
    const int* edst   = (const int*)d_in[11];
    float* out        = (float*)d_out;

    int N = in_sizes[0] / F_IN;
    int E = in_sizes[10];

    int nThr = 256;
    int nBlkN = (N + nThr - 1) / nThr;
    int nBlkE = (E + nThr - 1) / nThr;
    int nScanBlk = (N + 1023) / 1024;

    // Launch order puts gemm0 at slot 3 — the slot ncu captures —
    // so the next profile shows the dominant kernel. gemm0 is independent of
    // the CSR build, so this reorder is safe.
    zero_deg_kernel<<<nBlkN, nThr>>>(N);                 // 0
    count_kernel<<<nBlkE, nThr>>>(esrc, E);              // 1
    degfin_kernel<<<nBlkN, nThr>>>(N);                   // 2
    dim3 g0((N + 127) / 128, 4);
    gemm0_kernel<<<g0, 256>>>(x, Wm0, bm0, Wv0, bv0, N); // 3  <- profile target
    scan1_kernel<<<nScanBlk, 1024>>>(N);                 // 4
    scan2_kernel<<<1, 128>>>(nScanBlk);                  // 5
    scan3_kernel<<<nBlkN, nThr>>>(N, E);                 // 6
    scatter_kernel<<<nBlkE, nThr>>>(esrc, edst, E);      // 7
    gemm1_kernel<<<(N + 127) / 128, 256>>>(Wm1, bm1, Wv1, bv1, N);  // 8

    int warpsPerBlk = nThr / 32;
    spmm_final_kernel<<<(N + warpsPerBlk - 1) / warpsPerBlk, nThr>>>(samp, out, N);  // 9
}